// round 8
// baseline (speedup 1.0000x reference)
#include <cuda_runtime.h>
#include <cuda_bf16.h>

// SSIM loss, round 8: R4's high-occupancy layout (64x16 tiles, 4-row-group V
// phase, ~19.5KB smem) + round-6 packed f32x2 math. Upfront 14-row loads for
// MLP, 6 packed weight regs via window symmetry, 3+ blocks/SM.

#define TW 64
#define TH 16
#define RAD 5
#define INW 74          // TW + 2*RAD
#define HBW2 76         // hb row stride in u64 units (608B)
#define NITEMS (INW * 4)   // 296: (column, 4-row group)
#define HW 512
#define PLANE_ELEMS (512 * 512)
#define NBLOCKS 12288

#define W0 0.00102838f
#define W1 0.00759877f
#define W2 0.03600077f
#define W3 0.10936070f
#define W4 0.21300554f
#define W5 0.26601173f

typedef unsigned long long ull;

__device__ float g_partials[NBLOCKS];
__device__ unsigned int g_counter = 0;

__device__ __forceinline__ ull f2pack(float lo, float hi) {
    ull d;
    asm("mov.b64 %0, {%1, %2};" : "=l"(d) : "f"(lo), "f"(hi));
    return d;
}
__device__ __forceinline__ void f2unpack(float& lo, float& hi, ull v) {
    asm("mov.b64 {%0, %1}, %2;" : "=f"(lo), "=f"(hi) : "l"(v));
}
__device__ __forceinline__ ull fma2(ull a, ull b, ull c) {
    ull d;
    asm("fma.rn.f32x2 %0, %1, %2, %3;" : "=l"(d) : "l"(a), "l"(b), "l"(c));
    return d;
}
// symmetric window: 6 unique packed weights
#define WIDX(k) ((k) < 6 ? (k) : 10 - (k))

template<bool INTERIOR>
__device__ __forceinline__ void ssim_phase_v(
    const float* __restrict__ pp, const float* __restrict__ tt,
    int x0, int y0, int tid, ull* __restrict__ hb01, ull* __restrict__ hb23,
    const ull* __restrict__ Wb)
{
    for (int item = tid; item < NITEMS; item += 256) {
        int g = item / INW;          // row group (4 outputs)
        int c = item - g * INW;      // column
        int gx = x0 - RAD + c;
        int gybase = y0 + 4 * g - RAD;
        bool xok = INTERIOR || ((gx >= 0) && (gx < HW));
        const float* __restrict__ prow = pp + (size_t)gybase * HW + gx;
        const float* __restrict__ trow = tt + (size_t)gybase * HW + gx;

        // Load all 14 rows up front (high MLP).
        float p[14], t[14];
#pragma unroll
        for (int rr = 0; rr < 14; rr++) {
            if (INTERIOR) {
                p[rr] = __ldg(prow + rr * HW);
                t[rr] = __ldg(trow + rr * HW);
            } else {
                int gy = gybase + rr;
                p[rr] = 0.f; t[rr] = 0.f;
                if (xok && gy >= 0 && gy < HW) {
                    p[rr] = __ldg(prow + rr * HW);
                    t[rr] = __ldg(trow + rr * HW);
                }
            }
        }

        ull a01[4] = {0ull, 0ull, 0ull, 0ull};
        ull a23[4] = {0ull, 0ull, 0ull, 0ull};
#pragma unroll
        for (int rr = 0; rr < 14; rr++) {
            float sv = p[rr] + t[rr];
            float dv = p[rr] - t[rr];
            ull pt = f2pack(p[rr], t[rr]);
            ull sd = f2pack(sv * sv, dv * dv);
#pragma unroll
            for (int j = 0; j < 4; j++) {
                int k = rr - j;
                if (k >= 0 && k <= 10) {
                    a01[j] = fma2(Wb[WIDX(k)], pt, a01[j]);
                    a23[j] = fma2(Wb[WIDX(k)], sd, a23[j]);
                }
            }
        }
#pragma unroll
        for (int j = 0; j < 4; j++) {
            int row = 4 * g + j;
            hb01[row * HBW2 + c] = a01[j];
            hb23[row * HBW2 + c] = a23[j];
        }
    }
}

__global__ __launch_bounds__(256, 3) void ssim_main_kernel(
    const float* __restrict__ pred,
    const float* __restrict__ target,
    float* __restrict__ out,
    float inv_count)
{
    __shared__ __align__(16) ull hb01[TH * HBW2];   // 9728 B
    __shared__ __align__(16) ull hb23[TH * HBW2];   // 9728 B
    __shared__ float red[8];
    __shared__ bool s_last;

    const int tid = threadIdx.x;
    const int x0 = blockIdx.x * TW;
    const int y0 = blockIdx.y * TH;
    const size_t plane_off = (size_t)blockIdx.z * PLANE_ELEMS;
    const float* __restrict__ pp = pred + plane_off;
    const float* __restrict__ tt = target + plane_off;

    ull Wb[6];
    Wb[0] = f2pack(W0, W0);  Wb[1] = f2pack(W1, W1);
    Wb[2] = f2pack(W2, W2);  Wb[3] = f2pack(W3, W3);
    Wb[4] = f2pack(W4, W4);  Wb[5] = f2pack(W5, W5);

    // ---- Phase V ----
    const bool interior =
        (x0 >= RAD) && (x0 + TW + RAD <= HW) && (y0 >= RAD) && (y0 + TH + RAD <= HW);
    if (interior) ssim_phase_v<true >(pp, tt, x0, y0, tid, hb01, hb23, Wb);
    else          ssim_phase_v<false>(pp, tt, x0, y0, tid, hb01, hb23, Wb);
    __syncthreads();

    // ---- Phase H: one item/thread = 4 consecutive x in one row ----
    const float C1 = 0.0001f;
    const float C2 = 0.0009f;
    float local = 0.f;
    {
        int r = tid >> 4;                // 0..15
        int cg = (tid & 15) << 2;        // 0..60
        const ull* rb01 = hb01 + r * HBW2 + cg;
        const ull* rb23 = hb23 + r * HBW2 + cg;

        float mu1[4], mu2[4], css[4], cdd[4];
        {
            ull v[16];
#pragma unroll
            for (int q = 0; q < 8; q++) {
                ulonglong2 u = *(const ulonglong2*)(rb01 + 2 * q);
                v[2 * q] = u.x; v[2 * q + 1] = u.y;
            }
            ull acc[4] = {0ull, 0ull, 0ull, 0ull};
#pragma unroll
            for (int i = 0; i < 14; i++) {
#pragma unroll
                for (int j = 0; j < 4; j++) {
                    int k = i - j;
                    if (k >= 0 && k <= 10)
                        acc[j] = fma2(Wb[WIDX(k)], v[i], acc[j]);
                }
            }
#pragma unroll
            for (int j = 0; j < 4; j++) f2unpack(mu1[j], mu2[j], acc[j]);
        }
        {
            ull v[16];
#pragma unroll
            for (int q = 0; q < 8; q++) {
                ulonglong2 u = *(const ulonglong2*)(rb23 + 2 * q);
                v[2 * q] = u.x; v[2 * q + 1] = u.y;
            }
            ull acc[4] = {0ull, 0ull, 0ull, 0ull};
#pragma unroll
            for (int i = 0; i < 14; i++) {
#pragma unroll
                for (int j = 0; j < 4; j++) {
                    int k = i - j;
                    if (k >= 0 && k <= 10)
                        acc[j] = fma2(Wb[WIDX(k)], v[i], acc[j]);
                }
            }
#pragma unroll
            for (int j = 0; j < 4; j++) f2unpack(css[j], cdd[j], acc[j]);
        }

#pragma unroll
        for (int j = 0; j < 4; j++) {
            float m1 = mu1[j], m2 = mu2[j];
            float m1s = m1 * m1;
            float m2s = m2 * m2;
            float m12 = m1 * m2;
            float ept   = 0.25f * (css[j] - cdd[j]);   // E[pt]
            float epptt = 0.5f  * (css[j] + cdd[j]);   // E[pp]+E[tt]
            float s12  = ept - m12;
            float ssum = epptt - m1s - m2s;
            float num = (2.0f * m12 + C1) * (2.0f * s12 + C2);
            float den = (m1s + m2s + C1) * (ssum + C2);
            local += __fdividef(num, den);
        }
    }

    // ---- Block reduction -> partial; last block reduces globally ----
#pragma unroll
    for (int off = 16; off > 0; off >>= 1)
        local += __shfl_down_sync(0xffffffffu, local, off);
    if ((tid & 31) == 0) red[tid >> 5] = local;
    __syncthreads();
    if (tid == 0) {
        float v = red[0] + red[1] + red[2] + red[3]
                + red[4] + red[5] + red[6] + red[7];
        int bid = (blockIdx.z * gridDim.y + blockIdx.y) * gridDim.x + blockIdx.x;
        g_partials[bid] = v;
        __threadfence();
        unsigned int n = atomicAdd(&g_counter, 1u);
        s_last = (n == NBLOCKS - 1u);
    }
    __syncthreads();

    if (s_last) {
        __threadfence();
        __shared__ double dred[8];
        const float4* __restrict__ p4 = (const float4*)g_partials;
        double acc = 0.0;
#pragma unroll
        for (int i = 0; i < NBLOCKS / 4 / 256; i++) {    // 12 iterations
            float4 v = p4[i * 256 + tid];
            acc += (double)v.x + (double)v.y + (double)v.z + (double)v.w;
        }
#pragma unroll
        for (int off = 16; off > 0; off >>= 1)
            acc += __shfl_down_sync(0xffffffffu, acc, off);
        if ((tid & 31) == 0) dred[tid >> 5] = acc;
        __syncthreads();
        if (tid == 0) {
            double s = dred[0] + dred[1] + dred[2] + dred[3]
                     + dred[4] + dred[5] + dred[6] + dred[7];
            out[0] = 1.0f - (float)(s * (double)inv_count);
            g_counter = 0;   // reset for next graph replay
        }
    }
}

extern "C" void kernel_launch(void* const* d_in, const int* in_sizes, int n_in,
                              void* d_out, int out_size) {
    const float* pred = (const float*)d_in[0];
    const float* target = (const float*)d_in[1];
    float* out = (float*)d_out;

    const int total = in_sizes[0];                 // N*C*H*W
    const int nplanes = total / PLANE_ELEMS;       // 48

    dim3 grid(HW / TW, HW / TH, nplanes);          // (8, 32, 48) = 12288 blocks
    ssim_main_kernel<<<grid, 256>>>(pred, target, out, 1.0f / (float)total);
}

// round 9
// speedup vs baseline: 1.2836x; 1.2836x over previous
#include <cuda_runtime.h>
#include <cuda_bf16.h>

// SSIM loss, round 9: 128x32 tiles, fp32 ring-FIR vertical pass (16-row groups,
// 1.625 loads/px), immediate-form FFMA weights, 71.7KB smem, 3 blocks/SM.

#define TW 128
#define TH 32
#define RAD 5
#define INW 138         // TW + 2*RAD
#define HBW 140         // hb row stride in floats (16B multiple)
#define GROUPS 2        // 16-row groups
#define NITEMS (INW * GROUPS)   // 276
#define HW 512
#define PLANE_ELEMS (512 * 512)
#define NBLOCKS 3072

#define W0 0.00102838f
#define W1 0.00759877f
#define W2 0.03600077f
#define W3 0.10936070f
#define W4 0.21300554f
#define W5 0.26601173f

__device__ float g_partials[NBLOCKS];
__device__ unsigned int g_counter = 0;

// Vertical 11-tap conv of {p, t, (p+t)^2, (p-t)^2}: one column x 16 output
// rows per item, 11-deep fp32 accumulator ring, 26 row loads.
template<bool INTERIOR>
__device__ __forceinline__ void ssim_phase_v(
    const float* __restrict__ pp, const float* __restrict__ tt,
    int x0, int y0, int tid, float* __restrict__ hb)
{
    constexpr float W[11] = {W0, W1, W2, W3, W4, W5, W4, W3, W2, W1, W0};

    for (int item = tid; item < NITEMS; item += 256) {
        int g = item / INW;
        int c = item - g * INW;
        int gx = x0 - RAD + c;
        int gybase = y0 + 16 * g - RAD;
        bool xok = INTERIOR || ((gx >= 0) && (gx < HW));
        const float* __restrict__ prow = pp + (size_t)gybase * HW + gx;
        const float* __restrict__ trow = tt + (size_t)gybase * HW + gx;

        float a0[11], a1[11], a2[11], a3[11];
#pragma unroll
        for (int s = 0; s < 11; s++) { a0[s] = 0.f; a1[s] = 0.f; a2[s] = 0.f; a3[s] = 0.f; }

#pragma unroll
        for (int rr = 0; rr < 26; rr++) {
            float p, t;
            if (INTERIOR) {
                p = __ldg(prow + rr * HW);
                t = __ldg(trow + rr * HW);
            } else {
                int gy = gybase + rr;
                p = 0.f; t = 0.f;
                if (xok && gy >= 0 && gy < HW) {
                    p = __ldg(prow + rr * HW);
                    t = __ldg(trow + rr * HW);
                }
            }
            float sv = p + t;
            float dv = p - t;
            float ss = sv * sv;
            float dd = dv * dv;
#pragma unroll
            for (int j = 0; j < 16; j++) {
                int k = rr - j;
                if (k >= 0 && k <= 10) {
                    int slot = j % 11;
                    a0[slot] += W[k] * p;
                    a1[slot] += W[k] * t;
                    a2[slot] += W[k] * ss;
                    a3[slot] += W[k] * dd;
                }
            }
            if (rr >= 10) {
                int j = rr - 10;
                int slot = j % 11;
                int row = 16 * g + j;
                hb[(0 * TH + row) * HBW + c] = a0[slot];  a0[slot] = 0.f;
                hb[(1 * TH + row) * HBW + c] = a1[slot];  a1[slot] = 0.f;
                hb[(2 * TH + row) * HBW + c] = a2[slot];  a2[slot] = 0.f;
                hb[(3 * TH + row) * HBW + c] = a3[slot];  a3[slot] = 0.f;
            }
        }
    }
}

__global__ __launch_bounds__(256, 3) void ssim_main_kernel(
    const float* __restrict__ pred,
    const float* __restrict__ target,
    float* __restrict__ out,
    float inv_count)
{
    constexpr float W[11] = {W0, W1, W2, W3, W4, W5, W4, W3, W2, W1, W0};

    extern __shared__ __align__(16) float hb[];   // [4][32][140] = 71680 B
    __shared__ float red[8];
    __shared__ bool s_last;

    const int tid = threadIdx.x;
    const int x0 = blockIdx.x * TW;
    const int y0 = blockIdx.y * TH;
    const size_t plane_off = (size_t)blockIdx.z * PLANE_ELEMS;
    const float* __restrict__ pp = pred + plane_off;
    const float* __restrict__ tt = target + plane_off;

    // ---- Phase V ----
    const bool interior =
        (x0 >= RAD) && (x0 + TW + RAD <= HW) && (y0 >= RAD) && (y0 + TH + RAD <= HW);
    if (interior) ssim_phase_v<true >(pp, tt, x0, y0, tid, hb);
    else          ssim_phase_v<false>(pp, tt, x0, y0, tid, hb);
    __syncthreads();

    // ---- Phase H: 4 quads/thread; quad = 4 consecutive x in one row ----
    const float C1 = 0.0001f;
    const float C2 = 0.0009f;
    float local = 0.f;

#pragma unroll
    for (int it = 0; it < 4; it++) {
        int h = tid + 256 * it;           // 0..1023
        int r = h >> 5;                   // row 0..31
        int cg = (h & 31) << 2;           // x base 0..124
        const float* rb0 = hb + (0 * TH + r) * HBW + cg;
        const float* rb1 = hb + (1 * TH + r) * HBW + cg;
        const float* rb2 = hb + (2 * TH + r) * HBW + cg;
        const float* rb3 = hb + (3 * TH + r) * HBW + cg;

        float m1[4] = {0.f, 0.f, 0.f, 0.f};
        float m2[4] = {0.f, 0.f, 0.f, 0.f};
        // Batch 1: mu fields
        {
            float v0[16], v1[16];
#pragma unroll
            for (int q = 0; q < 4; q++) {
                float4 u;
                u = *(const float4*)(rb0 + 4 * q);
                v0[4*q] = u.x; v0[4*q+1] = u.y; v0[4*q+2] = u.z; v0[4*q+3] = u.w;
                u = *(const float4*)(rb1 + 4 * q);
                v1[4*q] = u.x; v1[4*q+1] = u.y; v1[4*q+2] = u.z; v1[4*q+3] = u.w;
            }
#pragma unroll
            for (int i = 0; i < 14; i++) {
#pragma unroll
                for (int j = 0; j < 4; j++) {
                    int k = i - j;
                    if (k >= 0 && k <= 10) {
                        m1[j] += W[k] * v0[i];
                        m2[j] += W[k] * v1[i];
                    }
                }
            }
        }
        float cs[4] = {0.f, 0.f, 0.f, 0.f};
        float cd[4] = {0.f, 0.f, 0.f, 0.f};
        // Batch 2: second-moment fields
        {
            float v2[16], v3[16];
#pragma unroll
            for (int q = 0; q < 4; q++) {
                float4 u;
                u = *(const float4*)(rb2 + 4 * q);
                v2[4*q] = u.x; v2[4*q+1] = u.y; v2[4*q+2] = u.z; v2[4*q+3] = u.w;
                u = *(const float4*)(rb3 + 4 * q);
                v3[4*q] = u.x; v3[4*q+1] = u.y; v3[4*q+2] = u.z; v3[4*q+3] = u.w;
            }
#pragma unroll
            for (int i = 0; i < 14; i++) {
#pragma unroll
                for (int j = 0; j < 4; j++) {
                    int k = i - j;
                    if (k >= 0 && k <= 10) {
                        cs[j] += W[k] * v2[i];
                        cd[j] += W[k] * v3[i];
                    }
                }
            }
        }

#pragma unroll
        for (int j = 0; j < 4; j++) {
            float mu1 = m1[j], mu2 = m2[j];
            float m1s = mu1 * mu1;
            float m2s = mu2 * mu2;
            float m12 = mu1 * mu2;
            float ept   = 0.25f * (cs[j] - cd[j]);    // E[pt]
            float epptt = 0.5f  * (cs[j] + cd[j]);    // E[pp]+E[tt]
            float s12  = ept - m12;
            float ssum = epptt - m1s - m2s;
            float num = (2.0f * m12 + C1) * (2.0f * s12 + C2);
            float den = (m1s + m2s + C1) * (ssum + C2);
            local += __fdividef(num, den);
        }
    }

    // ---- Block reduction -> partial; last block reduces globally ----
#pragma unroll
    for (int off = 16; off > 0; off >>= 1)
        local += __shfl_down_sync(0xffffffffu, local, off);
    if ((tid & 31) == 0) red[tid >> 5] = local;
    __syncthreads();
    if (tid == 0) {
        float v = red[0] + red[1] + red[2] + red[3]
                + red[4] + red[5] + red[6] + red[7];
        int bid = (blockIdx.z * gridDim.y + blockIdx.y) * gridDim.x + blockIdx.x;
        g_partials[bid] = v;
        __threadfence();
        unsigned int n = atomicAdd(&g_counter, 1u);
        s_last = (n == NBLOCKS - 1u);
    }
    __syncthreads();

    if (s_last) {
        __threadfence();
        __shared__ double dred[8];
        const float4* __restrict__ p4 = (const float4*)g_partials;
        double acc = 0.0;
#pragma unroll
        for (int i = 0; i < NBLOCKS / 4 / 256; i++) {   // 3 iterations
            float4 v = p4[i * 256 + tid];
            acc += (double)v.x + (double)v.y + (double)v.z + (double)v.w;
        }
#pragma unroll
        for (int off = 16; off > 0; off >>= 1)
            acc += __shfl_down_sync(0xffffffffu, acc, off);
        if ((tid & 31) == 0) dred[tid >> 5] = acc;
        __syncthreads();
        if (tid == 0) {
            double s = dred[0] + dred[1] + dred[2] + dred[3]
                     + dred[4] + dred[5] + dred[6] + dred[7];
            out[0] = 1.0f - (float)(s * (double)inv_count);
            g_counter = 0;
        }
    }
}

extern "C" void kernel_launch(void* const* d_in, const int* in_sizes, int n_in,
                              void* d_out, int out_size) {
    const float* pred = (const float*)d_in[0];
    const float* target = (const float*)d_in[1];
    float* out = (float*)d_out;

    const int total = in_sizes[0];                 // N*C*H*W
    const int nplanes = total / PLANE_ELEMS;       // 48

    const size_t smem = sizeof(float) * 4 * TH * HBW;   // 71680 B
    cudaFuncSetAttribute(ssim_main_kernel,
                         cudaFuncAttributeMaxDynamicSharedMemorySize, (int)smem);

    dim3 grid(HW / TW, HW / TH, nplanes);          // (4, 16, 48) = 3072 blocks
    ssim_main_kernel<<<grid, 256, smem>>>(pred, target, out, 1.0f / (float)total);
}

// round 10
// speedup vs baseline: 1.2949x; 1.0088x over previous
#include <cuda_runtime.h>
#include <cuda_bf16.h>

// SSIM loss, round 10: R9 layout (128x32 tiles, ring-FIR V phase, 71.7KB smem,
// 3 blocks/SM) + f32x2 packed math everywhere. Packed accumulators cost the
// same registers as scalar, but FFMA issue slots halve; FMA pipe becomes the
// binding resource.

#define TW 128
#define TH 32
#define RAD 5
#define INW 138         // TW + 2*RAD
#define HBW2 140        // hb row stride in u64 units (1120B)
#define GROUPS 2        // 16-row groups
#define NITEMS (INW * GROUPS)   // 276
#define HW 512
#define PLANE_ELEMS (512 * 512)
#define NBLOCKS 3072

#define W0 0.00102838f
#define W1 0.00759877f
#define W2 0.03600077f
#define W3 0.10936070f
#define W4 0.21300554f
#define W5 0.26601173f

typedef unsigned long long ull;

__device__ float g_partials[NBLOCKS];
__device__ unsigned int g_counter = 0;

__device__ __forceinline__ ull f2pack(float lo, float hi) {
    ull d;
    asm("mov.b64 %0, {%1, %2};" : "=l"(d) : "f"(lo), "f"(hi));
    return d;
}
__device__ __forceinline__ void f2unpack(float& lo, float& hi, ull v) {
    asm("mov.b64 {%0, %1}, %2;" : "=f"(lo), "=f"(hi) : "l"(v));
}
__device__ __forceinline__ ull fma2(ull a, ull b, ull c) {
    ull d;
    asm("fma.rn.f32x2 %0, %1, %2, %3;" : "=l"(d) : "l"(a), "l"(b), "l"(c));
    return d;
}
// symmetric 11-tap window: 6 unique weights
#define WIDX(k) ((k) < 6 ? (k) : 10 - (k))

// Vertical 11-tap conv: one column x 16 output rows per item, 11-deep packed
// accumulator ring (transposed FIR), 26 row loads. hb01 <- {conv p, conv t},
// hb23 <- {conv (p+t)^2, conv (p-t)^2}.
template<bool INTERIOR>
__device__ __forceinline__ void ssim_phase_v(
    const float* __restrict__ pp, const float* __restrict__ tt,
    int x0, int y0, int tid, ull* __restrict__ hb01, ull* __restrict__ hb23,
    const ull* __restrict__ Wb)
{
    for (int item = tid; item < NITEMS; item += 256) {
        int g = item / INW;
        int c = item - g * INW;
        int gx = x0 - RAD + c;
        int gybase = y0 + 16 * g - RAD;
        bool xok = INTERIOR || ((gx >= 0) && (gx < HW));
        const float* __restrict__ prow = pp + (size_t)gybase * HW + gx;
        const float* __restrict__ trow = tt + (size_t)gybase * HW + gx;

        ull a01[11], a23[11];
#pragma unroll
        for (int s = 0; s < 11; s++) { a01[s] = 0ull; a23[s] = 0ull; }

#pragma unroll
        for (int rr = 0; rr < 26; rr++) {
            float p, t;
            if (INTERIOR) {
                p = __ldg(prow + rr * HW);
                t = __ldg(trow + rr * HW);
            } else {
                int gy = gybase + rr;
                p = 0.f; t = 0.f;
                if (xok && gy >= 0 && gy < HW) {
                    p = __ldg(prow + rr * HW);
                    t = __ldg(trow + rr * HW);
                }
            }
            float sv = p + t;
            float dv = p - t;
            ull pt = f2pack(p, t);
            ull sd = f2pack(sv * sv, dv * dv);
#pragma unroll
            for (int j = 0; j < 16; j++) {
                int k = rr - j;
                if (k >= 0 && k <= 10) {
                    int slot = j % 11;
                    a01[slot] = fma2(Wb[WIDX(k)], pt, a01[slot]);
                    a23[slot] = fma2(Wb[WIDX(k)], sd, a23[slot]);
                }
            }
            if (rr >= 10) {
                int j = rr - 10;
                int slot = j % 11;
                int row = 16 * g + j;
                hb01[row * HBW2 + c] = a01[slot];  a01[slot] = 0ull;
                hb23[row * HBW2 + c] = a23[slot];  a23[slot] = 0ull;
            }
        }
    }
}

__global__ __launch_bounds__(256, 3) void ssim_main_kernel(
    const float* __restrict__ pred,
    const float* __restrict__ target,
    float* __restrict__ out,
    float inv_count)
{
    extern __shared__ __align__(16) ull smem_raw[];
    ull* hb01 = smem_raw;                   // [32][140] u64 = 35840 B
    ull* hb23 = smem_raw + TH * HBW2;       // [32][140] u64 = 35840 B
    __shared__ float red[8];
    __shared__ bool s_last;

    const int tid = threadIdx.x;
    const int x0 = blockIdx.x * TW;
    const int y0 = blockIdx.y * TH;
    const size_t plane_off = (size_t)blockIdx.z * PLANE_ELEMS;
    const float* __restrict__ pp = pred + plane_off;
    const float* __restrict__ tt = target + plane_off;

    ull Wb[6];
    Wb[0] = f2pack(W0, W0);  Wb[1] = f2pack(W1, W1);
    Wb[2] = f2pack(W2, W2);  Wb[3] = f2pack(W3, W3);
    Wb[4] = f2pack(W4, W4);  Wb[5] = f2pack(W5, W5);

    // ---- Phase V ----
    const bool interior =
        (x0 >= RAD) && (x0 + TW + RAD <= HW) && (y0 >= RAD) && (y0 + TH + RAD <= HW);
    if (interior) ssim_phase_v<true >(pp, tt, x0, y0, tid, hb01, hb23, Wb);
    else          ssim_phase_v<false>(pp, tt, x0, y0, tid, hb01, hb23, Wb);
    __syncthreads();

    // ---- Phase H: 4 quads/thread; quad = 4 consecutive x in one row ----
    const float C1 = 0.0001f;
    const float C2 = 0.0009f;
    float local = 0.f;

#pragma unroll
    for (int it = 0; it < 4; it++) {
        int h = tid + 256 * it;           // 0..1023
        int r = h >> 5;                   // row 0..31
        int cg = (h & 31) << 2;           // x base 0..124
        const ull* rb01 = hb01 + r * HBW2 + cg;
        const ull* rb23 = hb23 + r * HBW2 + cg;

        float mu1[4], mu2[4], css[4], cdd[4];
        // Batch 1: packed {mu1, mu2}
        {
            ull v[16];
#pragma unroll
            for (int q = 0; q < 8; q++) {
                ulonglong2 u = *(const ulonglong2*)(rb01 + 2 * q);
                v[2 * q] = u.x; v[2 * q + 1] = u.y;
            }
            ull acc[4] = {0ull, 0ull, 0ull, 0ull};
#pragma unroll
            for (int i = 0; i < 14; i++) {
#pragma unroll
                for (int j = 0; j < 4; j++) {
                    int k = i - j;
                    if (k >= 0 && k <= 10)
                        acc[j] = fma2(Wb[WIDX(k)], v[i], acc[j]);
                }
            }
#pragma unroll
            for (int j = 0; j < 4; j++) f2unpack(mu1[j], mu2[j], acc[j]);
        }
        // Batch 2: packed {css, cdd}
        {
            ull v[16];
#pragma unroll
            for (int q = 0; q < 8; q++) {
                ulonglong2 u = *(const ulonglong2*)(rb23 + 2 * q);
                v[2 * q] = u.x; v[2 * q + 1] = u.y;
            }
            ull acc[4] = {0ull, 0ull, 0ull, 0ull};
#pragma unroll
            for (int i = 0; i < 14; i++) {
#pragma unroll
                for (int j = 0; j < 4; j++) {
                    int k = i - j;
                    if (k >= 0 && k <= 10)
                        acc[j] = fma2(Wb[WIDX(k)], v[i], acc[j]);
                }
            }
#pragma unroll
            for (int j = 0; j < 4; j++) f2unpack(css[j], cdd[j], acc[j]);
        }

#pragma unroll
        for (int j = 0; j < 4; j++) {
            float m1 = mu1[j], m2 = mu2[j];
            float m1s = m1 * m1;
            float m2s = m2 * m2;
            float m12 = m1 * m2;
            float ept   = 0.25f * (css[j] - cdd[j]);   // E[pt]
            float epptt = 0.5f  * (css[j] + cdd[j]);   // E[pp]+E[tt]
            float s12  = ept - m12;
            float ssum = epptt - m1s - m2s;
            float num = (2.0f * m12 + C1) * (2.0f * s12 + C2);
            float den = (m1s + m2s + C1) * (ssum + C2);
            local += __fdividef(num, den);
        }
    }

    // ---- Block reduction -> partial; last block reduces globally ----
#pragma unroll
    for (int off = 16; off > 0; off >>= 1)
        local += __shfl_down_sync(0xffffffffu, local, off);
    if ((tid & 31) == 0) red[tid >> 5] = local;
    __syncthreads();
    if (tid == 0) {
        float v = red[0] + red[1] + red[2] + red[3]
                + red[4] + red[5] + red[6] + red[7];
        int bid = (blockIdx.z * gridDim.y + blockIdx.y) * gridDim.x + blockIdx.x;
        g_partials[bid] = v;
        __threadfence();
        unsigned int n = atomicAdd(&g_counter, 1u);
        s_last = (n == NBLOCKS - 1u);
    }
    __syncthreads();

    if (s_last) {
        __threadfence();
        __shared__ double dred[8];
        const float4* __restrict__ p4 = (const float4*)g_partials;
        double acc = 0.0;
#pragma unroll
        for (int i = 0; i < NBLOCKS / 4 / 256; i++) {   // 3 iterations
            float4 v = p4[i * 256 + tid];
            acc += (double)v.x + (double)v.y + (double)v.z + (double)v.w;
        }
#pragma unroll
        for (int off = 16; off > 0; off >>= 1)
            acc += __shfl_down_sync(0xffffffffu, acc, off);
        if ((tid & 31) == 0) dred[tid >> 5] = acc;
        __syncthreads();
        if (tid == 0) {
            double s = dred[0] + dred[1] + dred[2] + dred[3]
                     + dred[4] + dred[5] + dred[6] + dred[7];
            out[0] = 1.0f - (float)(s * (double)inv_count);
            g_counter = 0;
        }
    }
}

extern "C" void kernel_launch(void* const* d_in, const int* in_sizes, int n_in,
                              void* d_out, int out_size) {
    const float* pred = (const float*)d_in[0];
    const float* target = (const float*)d_in[1];
    float* out = (float*)d_out;

    const int total = in_sizes[0];                 // N*C*H*W
    const int nplanes = total / PLANE_ELEMS;       // 48

    const size_t smem = sizeof(ull) * 2 * TH * HBW2;   // 71680 B
    cudaFuncSetAttribute(ssim_main_kernel,
                         cudaFuncAttributeMaxDynamicSharedMemorySize, (int)smem);

    dim3 grid(HW / TW, HW / TH, nplanes);          // (4, 16, 48) = 3072 blocks
    ssim_main_kernel<<<grid, 256, smem>>>(pred, target, out, 1.0f / (float)total);
}